// round 16
// baseline (speedup 1.0000x reference)
#include <cuda_runtime.h>
#include <cuda_fp16.h>
#include <cstdint>

#define N_NODES 131072
#define KNBR    27
#define FIN     3
#define FOUT    32
#define CHUNK   256
#define NCHUNKS (N_NODES / CHUNK)   // 512
#define NPAIR   14                  // ceil(27/2) k-pairs in stage 1

// Scratch: h (fp16, fragment-permuted rows, 8MB) and fp16 permuted w2 (55KB).
// g_h[n*32 + perm32(c)] = h[n][c] => lane c4 reads its whole m16n8k16 A-slice
// of a row as ONE contiguous 16B chunk at byte offset c4*16 of the 64B row.
__device__ __half g_h[N_NODES * FOUT];
__device__ __half g_w2h[KNBR * FOUT * FOUT];

__device__ __forceinline__ int perm32(int c) {
    return ((c >> 1) & 3) * 8 + ((c >> 3) << 1) + (c & 1);
}
__device__ __forceinline__ uint32_t f2tf32(float x) {
    uint32_t r;
    asm("cvt.rna.tf32.f32 %0, %1;" : "=r"(r) : "f"(x));
    return r;
}
__device__ __forceinline__ uint32_t smem_u32(const void* p) {
    return (uint32_t)__cvta_generic_to_shared(p);
}
__device__ __forceinline__ void cp16(uint32_t dst, const void* src) {
    asm volatile("cp.async.cg.shared.global [%0], [%1], 16;"
                 :: "r"(dst), "l"(src) : "memory");
}
__device__ __forceinline__ void cp4(uint32_t dst, const void* src, int sz) {
    asm volatile("cp.async.ca.shared.global [%0], [%1], 4, %2;"
                 :: "r"(dst), "l"(src), "r"(sz) : "memory");
}
__device__ __forceinline__ void cp_commit() {
    asm volatile("cp.async.commit_group;" ::: "memory");
}
__device__ __forceinline__ void cp_wait3() {
    asm volatile("cp.async.wait_group 3;" ::: "memory");
}
__device__ __forceinline__ void cp_wait5() {
    asm volatile("cp.async.wait_group 5;" ::: "memory");
}

__device__ __forceinline__ void mma_tf32(float d[4], const uint32_t a[4],
                                         const uint32_t b[2]) {
    asm volatile(
        "mma.sync.aligned.m16n8k8.row.col.f32.tf32.tf32.f32 "
        "{%0,%1,%2,%3}, {%4,%5,%6,%7}, {%8,%9}, {%0,%1,%2,%3};"
        : "+f"(d[0]), "+f"(d[1]), "+f"(d[2]), "+f"(d[3])
        : "r"(a[0]), "r"(a[1]), "r"(a[2]), "r"(a[3]),
          "r"(b[0]), "r"(b[1]));
}
__device__ __forceinline__ void mma_f16(float d[4],
                                        uint32_t a0, uint32_t a1, uint32_t a2, uint32_t a3,
                                        uint32_t b0, uint32_t b1) {
    asm volatile(
        "mma.sync.aligned.m16n8k16.row.col.f32.f16.f16.f32 "
        "{%0,%1,%2,%3}, {%4,%5,%6,%7}, {%8,%9}, {%0,%1,%2,%3};"
        : "+f"(d[0]), "+f"(d[1]), "+f"(d[2]), "+f"(d[3])
        : "r"(a0), "r"(a1), "r"(a2), "r"(a3), "r"(b0), "r"(b1));
}

// ---------------------------------------------------------------------------
// Stage 1: h = BN+SiLU( sum_k x[nbr[n,k]] @ w1[k] ), tf32 mma with TWO
// neighbors packed per m16n8k8 (k=2j in A cols 0-3 / b0, k=2j+1 in cols 4-7
// / b1). 14 iterations instead of 27; MMA count halved. 512 threads, one
// 256-node chunk per CTA (grid=512, 2 CTAs/SM), warp owns 16 nodes.
// cp.async depth-6 gather pipeline (slots of 4 row-fragments x 128B).
// Blocks 0..26 also convert w2[k] into permuted g_w2h.
// Epilogue: BN+SiLU -> fp16 permuted g_h rows via smem, coalesced STG.128.
// ---------------------------------------------------------------------------
#define S1_W1    0                                // uint2 w1p: 14336B
#define S1_SC    (NPAIR * 32 * 4 * 8)             // 14336
#define S1_SH    (S1_SC + 128)                    // 14464
#define S1_STG   (S1_SH + 128)                    // 14592 (16B aligned)
#define S1_BUF   (S1_STG + 16 * 3072)             // 63744
#define S1_SMEM  (S1_BUF + 16 * 1024)             // 80128

__global__ __launch_bounds__(512, 2) void stage1_kernel(
    const float* __restrict__ x, const int* __restrict__ nbr,
    const float* __restrict__ w1, const float* __restrict__ w2,
    const float* __restrict__ bg, const float* __restrict__ bb,
    const float* __restrict__ bm, const float* __restrict__ bv)
{
    extern __shared__ char smem[];
    uint2* w1p = (uint2*)(smem + S1_W1);
    float* sc  = (float*)(smem + S1_SC);
    float* sh  = (float*)(smem + S1_SH);

    const int tid = threadIdx.x;
    const int nbase = blockIdx.x * CHUNK;

    // Side job: blocks 0..26 convert w2[k] -> g_w2h (fp16, fragment-permuted).
    if (blockIdx.x < KNBR) {
        int k = blockIdx.x;
        for (int i = tid; i < FOUT * FOUT; i += 512) {
            int c = i >> 5, o = i & 31;
            g_w2h[(k * 32 + o) * 32 + perm32(c)] =
                __float2half_rn(w2[k * 1024 + c * 32 + o]);
        }
    }
    // w1p[(j*32+o)*4 + c] = { w1[2j, c, o], w1[2j+1, c, o] } (zeros padded).
    for (int i = tid; i < NPAIR * 32 * 4; i += 512) {
        int j = i >> 7, o = (i >> 2) & 31, c = i & 3;
        int k0 = 2 * j, k1 = 2 * j + 1;
        uint2 v;
        v.x = (c < FIN) ? f2tf32(w1[(k0 * FIN + c) * FOUT + o]) : 0u;
        v.y = (c < FIN && k1 < KNBR) ? f2tf32(w1[(k1 * FIN + c) * FOUT + o]) : 0u;
        w1p[i] = v;
    }
    if (tid < 32) {
        float s = bg[tid] * rsqrtf(bv[tid] + 1e-5f);
        sc[tid] = s;
        sh[tid] = bb[tid] - bm[tid] * s;
    }
    __syncthreads();

    const int warp = tid >> 5, lane = tid & 31;
    const int g = lane >> 2, c4 = lane & 3;
    const int* nbrp0 = nbr + (size_t)(nbase + warp * 16 + g) * KNBR;
    const int* nbrp1 = nbrp0 + 8 * KNBR;
    const uint32_t stg = smem_u32(smem + S1_STG) + warp * 3072;
    const float* stgf = (const float*)(smem + S1_STG + warp * 3072);
    const int csz = (c4 < FIN) ? 4 : 0;
    const int coff = (c4 < FIN) ? c4 : 0;
    __half* buf = (__half*)(smem + S1_BUF) + warp * 512;

    float acc[4][4];
    #pragma unroll
    for (int nf = 0; nf < 4; nf++)
        #pragma unroll
        for (int i = 0; i < 4; i++) acc[nf][i] = 0.0f;

#define ISSUE1(jj, slot) { \
    int jc = (jj); \
    if (jc < NPAIR) { \
        int k0 = 2 * jc; \
        int k1 = (k0 + 1 < KNBR) ? k0 + 1 : KNBR - 1;  /* pad pair: b1=0 */ \
        int ra = __ldg(nbrp0 + k0), rb = __ldg(nbrp1 + k0); \
        int rc = __ldg(nbrp0 + k1), rd = __ldg(nbrp1 + k1); \
        uint32_t d = stg + (slot) * 512 + lane * 4; \
        cp4(d,       x + ra * FIN + coff, csz); \
        cp4(d + 128, x + rb * FIN + coff, csz); \
        cp4(d + 256, x + rc * FIN + coff, csz); \
        cp4(d + 384, x + rd * FIN + coff, csz); \
    } \
    cp_commit(); }

    ISSUE1(0, 0); ISSUE1(1, 1); ISSUE1(2, 2); ISSUE1(3, 3); ISSUE1(4, 4);
    int su = 0, si = 5;
    #pragma unroll 1
    for (int j = 0; j < NPAIR; j++) {
        ISSUE1(j + 5, si);
        cp_wait5();
        uint32_t a[4];
        a[0] = f2tf32(stgf[su * 128 + lane]);
        a[1] = f2tf32(stgf[su * 128 + 32 + lane]);
        a[2] = f2tf32(stgf[su * 128 + 64 + lane]);
        a[3] = f2tf32(stgf[su * 128 + 96 + lane]);
        #pragma unroll
        for (int nf = 0; nf < 4; nf++) {
            uint2 bw = w1p[(j * 32 + nf * 8 + g) * 4 + c4];
            uint32_t b[2] = { bw.x, bw.y };
            mma_tf32(acc[nf], a, b);
        }
        if (++su == 6) su = 0;
        if (++si == 6) si = 0;
    }
#undef ISSUE1

    // BN + SiLU -> fp16 permuted smem tile -> coalesced 16B stores.
    #pragma unroll
    for (int nf = 0; nf < 4; nf++)
        #pragma unroll
        for (int i = 0; i < 4; i++) {
            int o  = nf * 8 + 2 * c4 + (i & 1);
            int nl = g + ((i >> 1) << 3);
            float v = acc[nf][i] * sc[o] + sh[o];
            float s = v * (1.0f / (1.0f + __expf(-v)));
            buf[nl * 32 + perm32(o)] = __float2half_rn(s);
        }
    __syncwarp();
    uint4* dst = (uint4*)(g_h + (size_t)(nbase + warp * 16) * FOUT);
    const uint4* src = (const uint4*)buf;
    dst[lane] = src[lane];
    dst[32 + lane] = src[32 + lane];
}

// ---------------------------------------------------------------------------
// Stage 2: fp16 m16n8k16 gather-GEMM over g_h + point branch + fused output.
// 256 threads (8 warps), warp owns 32 nodes (2 m16 tiles) -> W fragments and
// indices amortized over 2x nodes. One 256-node chunk per CTA (grid=512),
// 3 CTAs/SM (85-reg cap). h gathers via cp.async.cg 4-slot ring (2KB/slot/
// warp, wait_group 3 => 3 k-periods of slack). W from g_w2h LDG.128
// (L1-resident). No block barriers in the hot loop.
// ---------------------------------------------------------------------------
#define S2_MW   0                             // 384B
#define S2_PA   (S2_MW + 96 * 4)              // 384
#define S2_PB   (S2_PA + 128)                 // 512
#define S2_STG  1024                          // 16B aligned
#define S2_SMEM (S2_STG + 8 * 8192)           // 66560

__global__ __launch_bounds__(256, 3) void stage2_kernel(
    const int* __restrict__ nbr,
    const float* __restrict__ zf,
    const float* __restrict__ mlpw, const float* __restrict__ mlpb,
    const float* __restrict__ mg, const float* __restrict__ mb2,
    const float* __restrict__ mm, const float* __restrict__ mv,
    float* __restrict__ out)
{
    extern __shared__ char smem[];
    float* mw_s = (float*)(smem + S2_MW);
    float* pA   = (float*)(smem + S2_PA);
    float* pB   = (float*)(smem + S2_PB);

    const int tid = threadIdx.x;
    const int warp = tid >> 5, lane = tid & 31;
    const int g = lane >> 2, c4 = lane & 3;
    const int nbase = blockIdx.x * CHUNK;
    const int wbase = nbase + warp * 32;

    for (int i = tid; i < FIN * FOUT; i += 256) mw_s[i] = mlpw[i];
    if (tid < 32) {
        float s = mg[tid] * rsqrtf(mv[tid] + 1e-5f);
        pA[tid] = s;
        pB[tid] = mlpb[tid] * s + mb2[tid] - mm[tid] * s;
    }
    __syncthreads();

    const char*  hBc = (const char*)g_h + (c4 << 4);
    const uint4* w2v = (const uint4*)g_w2h;
    const int* nbrB = nbr + (size_t)wbase * KNBR;
    const int off0 = g * KNBR, off1 = (8 + g) * KNBR;
    const int off2 = (16 + g) * KNBR, off3 = (24 + g) * KNBR;
    const uint32_t stg = smem_u32(smem + S2_STG) + warp * 8192;
    const uint4* stgv = (const uint4*)(smem + S2_STG + warp * 8192);

    float acc[2][4][4];
    #pragma unroll
    for (int t = 0; t < 2; t++)
        #pragma unroll
        for (int nf = 0; nf < 4; nf++)
            #pragma unroll
            for (int i = 0; i < 4; i++) acc[t][nf][i] = 0.0f;

#define ISSUE2(kk, slot) { \
    int kc = (kk); \
    if (kc < KNBR) { \
        uint32_t d = stg + (slot) * 2048 + lane * 16; \
        int r0 = __ldg(nbrB + off0 + kc); \
        int r1 = __ldg(nbrB + off1 + kc); \
        int r2 = __ldg(nbrB + off2 + kc); \
        int r3 = __ldg(nbrB + off3 + kc); \
        cp16(d,        hBc + ((size_t)r0 << 6)); \
        cp16(d + 512,  hBc + ((size_t)r1 << 6)); \
        cp16(d + 1024, hBc + ((size_t)r2 << 6)); \
        cp16(d + 1536, hBc + ((size_t)r3 << 6)); \
    } \
    cp_commit(); }

    ISSUE2(0, 0); ISSUE2(1, 1); ISSUE2(2, 2);
    int su = 0, si = 3;
    #pragma unroll 1
    for (int k = 0; k < KNBR; k++) {
        ISSUE2(k + 3, si);
        cp_wait3();
        uint4 A0 = stgv[su * 128 + lane];
        uint4 A1 = stgv[su * 128 + 32 + lane];
        uint4 A2 = stgv[su * 128 + 64 + lane];
        uint4 A3 = stgv[su * 128 + 96 + lane];
        #pragma unroll
        for (int nf = 0; nf < 4; nf++) {
            uint4 W = __ldg(w2v + ((k * 32 + nf * 8 + g) << 2) + c4);
            mma_f16(acc[0][nf], A0.x, A1.x, A0.y, A1.y, W.x, W.y);
            mma_f16(acc[0][nf], A0.z, A1.z, A0.w, A1.w, W.z, W.w);
            mma_f16(acc[1][nf], A2.x, A3.x, A2.y, A3.y, W.x, W.y);
            mma_f16(acc[1][nf], A2.z, A3.z, A2.w, A3.w, W.z, W.w);
        }
        if (++su == 4) su = 0;
        if (++si == 4) si = 0;
    }
#undef ISSUE2

    // Epilogue: point branch + fuse; write both output copies.
    #pragma unroll
    for (int t = 0; t < 2; t++) {
        int n0 = wbase + t * 16 + g;
        float z00 = zf[n0 * 3], z01 = zf[n0 * 3 + 1], z02 = zf[n0 * 3 + 2];
        float z10 = zf[(n0 + 8) * 3], z11 = zf[(n0 + 8) * 3 + 1], z12 = zf[(n0 + 8) * 3 + 2];
        #pragma unroll
        for (int nf = 0; nf < 4; nf++) {
            int o0 = nf * 8 + 2 * c4;
            float w0a = mw_s[o0],     w1a = mw_s[32 + o0],     w2a = mw_s[64 + o0];
            float w0b = mw_s[o0 + 1], w1b = mw_s[32 + o0 + 1], w2b = mw_s[64 + o0 + 1];
            float sA0 = pA[o0], sB0 = pB[o0], sA1 = pA[o0 + 1], sB1 = pB[o0 + 1];

            float d0 = z00 * w0a + z01 * w1a + z02 * w2a;
            float d1 = z00 * w0b + z01 * w1b + z02 * w2b;
            float e0 = z10 * w0a + z11 * w1a + z12 * w2a;
            float e1 = z10 * w0b + z11 * w1b + z12 * w2b;

            float2 lo, hi;
            lo.x = acc[t][nf][0] + fmaxf(d0 * sA0 + sB0, 0.0f);
            lo.y = acc[t][nf][1] + fmaxf(d1 * sA1 + sB1, 0.0f);
            hi.x = acc[t][nf][2] + fmaxf(e0 * sA0 + sB0, 0.0f);
            hi.y = acc[t][nf][3] + fmaxf(e1 * sA1 + sB1, 0.0f);

            size_t half = (size_t)N_NODES * FOUT;
            *(float2*)(out + (size_t)n0 * FOUT + o0)              = lo;
            *(float2*)(out + half + (size_t)n0 * FOUT + o0)       = lo;
            *(float2*)(out + (size_t)(n0 + 8) * FOUT + o0)        = hi;
            *(float2*)(out + half + (size_t)(n0 + 8) * FOUT + o0) = hi;
        }
    }
}

// ---------------------------------------------------------------------------

extern "C" void kernel_launch(void* const* d_in, const int* in_sizes, int n_in,
                              void* d_out, int out_size) {
    (void)in_sizes; (void)n_in; (void)out_size;
    const float* x    = (const float*)d_in[0];
    const float* z    = (const float*)d_in[1];
    const int*   nbr  = (const int*)  d_in[2];
    const float* w1   = (const float*)d_in[3];
    const float* bg   = (const float*)d_in[4];
    const float* bb   = (const float*)d_in[5];
    const float* bm   = (const float*)d_in[6];
    const float* bv   = (const float*)d_in[7];
    const float* w2   = (const float*)d_in[8];
    const float* mlpw = (const float*)d_in[9];
    const float* mlpb = (const float*)d_in[10];
    const float* mg   = (const float*)d_in[11];
    const float* mb2  = (const float*)d_in[12];
    const float* mm   = (const float*)d_in[13];
    const float* mv   = (const float*)d_in[14];
    float* out = (float*)d_out;

    cudaFuncSetAttribute(stage1_kernel, cudaFuncAttributeMaxDynamicSharedMemorySize, S1_SMEM);
    cudaFuncSetAttribute(stage2_kernel, cudaFuncAttributeMaxDynamicSharedMemorySize, S2_SMEM);

    stage1_kernel<<<NCHUNKS, 512, S1_SMEM>>>(x, nbr, w1, w2, bg, bb, bm, bv);
    stage2_kernel<<<NCHUNKS, 256, S2_SMEM>>>(nbr, z, mlpw, mlpb, mg, mb2, mm, mv, out);
}

// round 17
// speedup vs baseline: 1.1368x; 1.1368x over previous
#include <cuda_runtime.h>
#include <cuda_fp16.h>
#include <cstdint>

#define N_NODES 131072
#define KNBR    27
#define FIN     3
#define FOUT    32
#define CHUNK   256
#define NCHUNKS (N_NODES / CHUNK)   // 512
#define NPAIR   14                  // ceil(27/2) k-pairs in stage 1

// Scratch: h (fp16, fragment-permuted rows, 8MB) and fp16 permuted w2 (55KB,
// L1-resident broadcast weight table).
// g_h[n*32 + perm32(c)] = h[n][c] => lane c4 reads its whole m16n8k16 A-slice
// of a row as ONE contiguous 16B chunk at byte offset c4*16 of the 64B row.
__device__ __half g_h[N_NODES * FOUT];
__device__ __half g_w2h[KNBR * FOUT * FOUT];

__device__ __forceinline__ int perm32(int c) {
    return ((c >> 1) & 3) * 8 + ((c >> 3) << 1) + (c & 1);
}
__device__ __forceinline__ uint32_t f2tf32(float x) {
    uint32_t r;
    asm("cvt.rna.tf32.f32 %0, %1;" : "=r"(r) : "f"(x));
    return r;
}
__device__ __forceinline__ uint32_t smem_u32(const void* p) {
    return (uint32_t)__cvta_generic_to_shared(p);
}
__device__ __forceinline__ void cp16(uint32_t dst, const void* src) {
    asm volatile("cp.async.cg.shared.global [%0], [%1], 16;"
                 :: "r"(dst), "l"(src) : "memory");
}
__device__ __forceinline__ void cp4(uint32_t dst, const void* src, int sz) {
    asm volatile("cp.async.ca.shared.global [%0], [%1], 4, %2;"
                 :: "r"(dst), "l"(src), "r"(sz) : "memory");
}
__device__ __forceinline__ void cp_commit() {
    asm volatile("cp.async.commit_group;" ::: "memory");
}
__device__ __forceinline__ void cp_wait5() {
    asm volatile("cp.async.wait_group 5;" ::: "memory");
}

__device__ __forceinline__ void mma_tf32(float d[4], const uint32_t a[4],
                                         const uint32_t b[2]) {
    asm volatile(
        "mma.sync.aligned.m16n8k8.row.col.f32.tf32.tf32.f32 "
        "{%0,%1,%2,%3}, {%4,%5,%6,%7}, {%8,%9}, {%0,%1,%2,%3};"
        : "+f"(d[0]), "+f"(d[1]), "+f"(d[2]), "+f"(d[3])
        : "r"(a[0]), "r"(a[1]), "r"(a[2]), "r"(a[3]),
          "r"(b[0]), "r"(b[1]));
}
__device__ __forceinline__ void mma_f16(float d[4],
                                        uint32_t a0, uint32_t a1, uint32_t a2, uint32_t a3,
                                        uint32_t b0, uint32_t b1) {
    asm volatile(
        "mma.sync.aligned.m16n8k16.row.col.f32.f16.f16.f32 "
        "{%0,%1,%2,%3}, {%4,%5,%6,%7}, {%8,%9}, {%0,%1,%2,%3};"
        : "+f"(d[0]), "+f"(d[1]), "+f"(d[2]), "+f"(d[3])
        : "r"(a0), "r"(a1), "r"(a2), "r"(a3), "r"(b0), "r"(b1));
}

// ---------------------------------------------------------------------------
// Stage 1 (R16 winner): h = BN+SiLU( sum_k x[nbr[n,k]] @ w1[k] ), tf32 mma
// with TWO neighbors packed per m16n8k8 (k=2j in A cols 0-3 / b0, k=2j+1 in
// cols 4-7 / b1). 14 iterations; MMA count halved. 512 threads, one 256-node
// chunk per CTA (grid=512, 2 CTAs/SM), warp owns 16 nodes. cp.async depth-6
// gather pipeline (slots of 4 row-fragments x 128B). Blocks 0..26 also
// convert w2[k] into permuted g_w2h.
// Epilogue: BN+SiLU -> fp16 permuted g_h rows via smem, coalesced STG.128.
// ---------------------------------------------------------------------------
#define S1_W1    0                                // uint2 w1p: 14336B
#define S1_SC    (NPAIR * 32 * 4 * 8)             // 14336
#define S1_SH    (S1_SC + 128)                    // 14464
#define S1_STG   (S1_SH + 128)                    // 14592 (16B aligned)
#define S1_BUF   (S1_STG + 16 * 3072)             // 63744
#define S1_SMEM  (S1_BUF + 16 * 1024)             // 80128

__global__ __launch_bounds__(512, 2) void stage1_kernel(
    const float* __restrict__ x, const int* __restrict__ nbr,
    const float* __restrict__ w1, const float* __restrict__ w2,
    const float* __restrict__ bg, const float* __restrict__ bb,
    const float* __restrict__ bm, const float* __restrict__ bv)
{
    extern __shared__ char smem[];
    uint2* w1p = (uint2*)(smem + S1_W1);
    float* sc  = (float*)(smem + S1_SC);
    float* sh  = (float*)(smem + S1_SH);

    const int tid = threadIdx.x;
    const int nbase = blockIdx.x * CHUNK;

    if (blockIdx.x < KNBR) {
        int k = blockIdx.x;
        for (int i = tid; i < FOUT * FOUT; i += 512) {
            int c = i >> 5, o = i & 31;
            g_w2h[(k * 32 + o) * 32 + perm32(c)] =
                __float2half_rn(w2[k * 1024 + c * 32 + o]);
        }
    }
    for (int i = tid; i < NPAIR * 32 * 4; i += 512) {
        int j = i >> 7, o = (i >> 2) & 31, c = i & 3;
        int k0 = 2 * j, k1 = 2 * j + 1;
        uint2 v;
        v.x = (c < FIN) ? f2tf32(w1[(k0 * FIN + c) * FOUT + o]) : 0u;
        v.y = (c < FIN && k1 < KNBR) ? f2tf32(w1[(k1 * FIN + c) * FOUT + o]) : 0u;
        w1p[i] = v;
    }
    if (tid < 32) {
        float s = bg[tid] * rsqrtf(bv[tid] + 1e-5f);
        sc[tid] = s;
        sh[tid] = bb[tid] - bm[tid] * s;
    }
    __syncthreads();

    const int warp = tid >> 5, lane = tid & 31;
    const int g = lane >> 2, c4 = lane & 3;
    const int* nbrp0 = nbr + (size_t)(nbase + warp * 16 + g) * KNBR;
    const int* nbrp1 = nbrp0 + 8 * KNBR;
    const uint32_t stg = smem_u32(smem + S1_STG) + warp * 3072;
    const float* stgf = (const float*)(smem + S1_STG + warp * 3072);
    const int csz = (c4 < FIN) ? 4 : 0;
    const int coff = (c4 < FIN) ? c4 : 0;
    __half* buf = (__half*)(smem + S1_BUF) + warp * 512;

    float acc[4][4];
    #pragma unroll
    for (int nf = 0; nf < 4; nf++)
        #pragma unroll
        for (int i = 0; i < 4; i++) acc[nf][i] = 0.0f;

#define ISSUE1(jj, slot) { \
    int jc = (jj); \
    if (jc < NPAIR) { \
        int k0 = 2 * jc; \
        int k1 = (k0 + 1 < KNBR) ? k0 + 1 : KNBR - 1;  /* pad pair: b1=0 */ \
        int ra = __ldg(nbrp0 + k0), rb = __ldg(nbrp1 + k0); \
        int rc = __ldg(nbrp0 + k1), rd = __ldg(nbrp1 + k1); \
        uint32_t d = stg + (slot) * 512 + lane * 4; \
        cp4(d,       x + ra * FIN + coff, csz); \
        cp4(d + 128, x + rb * FIN + coff, csz); \
        cp4(d + 256, x + rc * FIN + coff, csz); \
        cp4(d + 384, x + rd * FIN + coff, csz); \
    } \
    cp_commit(); }

    ISSUE1(0, 0); ISSUE1(1, 1); ISSUE1(2, 2); ISSUE1(3, 3); ISSUE1(4, 4);
    int su = 0, si = 5;
    #pragma unroll 1
    for (int j = 0; j < NPAIR; j++) {
        ISSUE1(j + 5, si);
        cp_wait5();
        uint32_t a[4];
        a[0] = f2tf32(stgf[su * 128 + lane]);
        a[1] = f2tf32(stgf[su * 128 + 32 + lane]);
        a[2] = f2tf32(stgf[su * 128 + 64 + lane]);
        a[3] = f2tf32(stgf[su * 128 + 96 + lane]);
        #pragma unroll
        for (int nf = 0; nf < 4; nf++) {
            uint2 bw = w1p[(j * 32 + nf * 8 + g) * 4 + c4];
            uint32_t b[2] = { bw.x, bw.y };
            mma_tf32(acc[nf], a, b);
        }
        if (++su == 6) su = 0;
        if (++si == 6) si = 0;
    }
#undef ISSUE1

    // BN + SiLU -> fp16 permuted smem tile -> coalesced 16B stores.
    #pragma unroll
    for (int nf = 0; nf < 4; nf++)
        #pragma unroll
        for (int i = 0; i < 4; i++) {
            int o  = nf * 8 + 2 * c4 + (i & 1);
            int nl = g + ((i >> 1) << 3);
            float v = acc[nf][i] * sc[o] + sh[o];
            float s = v * (1.0f / (1.0f + __expf(-v)));
            buf[nl * 32 + perm32(o)] = __float2half_rn(s);
        }
    __syncwarp();
    uint4* dst = (uint4*)(g_h + (size_t)(nbase + warp * 16) * FOUT);
    const uint4* src = (const uint4*)buf;
    dst[lane] = src[lane];
    dst[32 + lane] = src[32 + lane];
}

// ---------------------------------------------------------------------------
// Stage 2 (R14 winner): fp16 m16n8k16 gather-GEMM over g_h + point branch +
// fused output. 512 threads, one 256-node chunk per CTA (grid=512), 2 CTAs/SM
// (32 warps). Warp owns 16 nodes. h gathers via cp.async.cg (16B) depth-6
// pipeline into per-warp smem slots (6 slots x 1KB). Indices via __ldg
// (per-row contiguous walk -> L1 hits). No block barriers in the hot loop.
// W fragments from g_w2h via LDG.128 (55KB table, L1-resident broadcast).
// ---------------------------------------------------------------------------
#define S2_MW   0                             // 384B
#define S2_PA   (S2_MW + 96 * 4)              // 384
#define S2_PB   (S2_PA + 128)                 // 512
#define S2_STG  1024                          // 16B aligned
#define S2_SMEM (S2_STG + 16 * 6144)          // 99328

__global__ __launch_bounds__(512, 2) void stage2_kernel(
    const int* __restrict__ nbr,
    const float* __restrict__ zf,
    const float* __restrict__ mlpw, const float* __restrict__ mlpb,
    const float* __restrict__ mg, const float* __restrict__ mb2,
    const float* __restrict__ mm, const float* __restrict__ mv,
    float* __restrict__ out)
{
    extern __shared__ char smem[];
    float* mw_s = (float*)(smem + S2_MW);
    float* pA   = (float*)(smem + S2_PA);
    float* pB   = (float*)(smem + S2_PB);

    const int tid = threadIdx.x;
    const int nbase = blockIdx.x * CHUNK;

    for (int i = tid; i < FIN * FOUT; i += 512) mw_s[i] = mlpw[i];
    if (tid < 32) {
        float s = mg[tid] * rsqrtf(mv[tid] + 1e-5f);
        pA[tid] = s;
        pB[tid] = mlpb[tid] * s + mb2[tid] - mm[tid] * s;
    }
    __syncthreads();

    const int warp = tid >> 5, lane = tid & 31;
    const int g = lane >> 2, c4 = lane & 3;
    const char*  hBc  = (const char*)g_h + (c4 << 4);
    const uint4* w2v  = (const uint4*)g_w2h;
    const int* nbrp0 = nbr + (size_t)(nbase + warp * 16 + g) * KNBR;
    const int* nbrp1 = nbrp0 + 8 * KNBR;
    const uint32_t stg = smem_u32(smem + S2_STG) + warp * 6144;
    const uint4* stgv = (const uint4*)(smem + S2_STG + warp * 6144);

    float acc[4][4];
    #pragma unroll
    for (int nf = 0; nf < 4; nf++)
        #pragma unroll
        for (int i = 0; i < 4; i++) acc[nf][i] = 0.0f;

#define ISSUE2(kk, slot) { \
    int kc = (kk); \
    if (kc < KNBR) { \
        int r0 = __ldg(nbrp0 + kc); \
        int r1 = __ldg(nbrp1 + kc); \
        cp16(stg + (slot) * 1024 + lane * 16,       hBc + ((size_t)r0 << 6)); \
        cp16(stg + (slot) * 1024 + 512 + lane * 16, hBc + ((size_t)r1 << 6)); \
    } \
    cp_commit(); }

    ISSUE2(0, 0); ISSUE2(1, 1); ISSUE2(2, 2); ISSUE2(3, 3); ISSUE2(4, 4);
    int su = 0, si = 5;
    #pragma unroll 1
    for (int k = 0; k < KNBR; k++) {
        ISSUE2(k + 5, si);
        cp_wait5();
        uint4 A0 = stgv[su * 64 + lane];
        uint4 A1 = stgv[su * 64 + 32 + lane];
        #pragma unroll
        for (int nf = 0; nf < 4; nf++) {
            uint4 W = __ldg(w2v + ((k * 32 + nf * 8 + g) << 2) + c4);
            mma_f16(acc[nf], A0.x, A1.x, A0.y, A1.y, W.x, W.y);
            mma_f16(acc[nf], A0.z, A1.z, A0.w, A1.w, W.z, W.w);
        }
        if (++su == 6) su = 0;
        if (++si == 6) si = 0;
    }
#undef ISSUE2

    // Epilogue: point branch + fuse; write both output copies.
    {
        int n0 = nbase + warp * 16 + g;
        float z00 = zf[n0 * 3], z01 = zf[n0 * 3 + 1], z02 = zf[n0 * 3 + 2];
        float z10 = zf[(n0 + 8) * 3], z11 = zf[(n0 + 8) * 3 + 1], z12 = zf[(n0 + 8) * 3 + 2];
        #pragma unroll
        for (int nf = 0; nf < 4; nf++) {
            int o0 = nf * 8 + 2 * c4;
            float w0a = mw_s[o0],     w1a = mw_s[32 + o0],     w2a = mw_s[64 + o0];
            float w0b = mw_s[o0 + 1], w1b = mw_s[32 + o0 + 1], w2b = mw_s[64 + o0 + 1];
            float sA0 = pA[o0], sB0 = pB[o0], sA1 = pA[o0 + 1], sB1 = pB[o0 + 1];

            float d0 = z00 * w0a + z01 * w1a + z02 * w2a;
            float d1 = z00 * w0b + z01 * w1b + z02 * w2b;
            float e0 = z10 * w0a + z11 * w1a + z12 * w2a;
            float e1 = z10 * w0b + z11 * w1b + z12 * w2b;

            float2 lo, hi;
            lo.x = acc[nf][0] + fmaxf(d0 * sA0 + sB0, 0.0f);
            lo.y = acc[nf][1] + fmaxf(d1 * sA1 + sB1, 0.0f);
            hi.x = acc[nf][2] + fmaxf(e0 * sA0 + sB0, 0.0f);
            hi.y = acc[nf][3] + fmaxf(e1 * sA1 + sB1, 0.0f);

            size_t half = (size_t)N_NODES * FOUT;
            *(float2*)(out + (size_t)n0 * FOUT + o0)              = lo;
            *(float2*)(out + half + (size_t)n0 * FOUT + o0)       = lo;
            *(float2*)(out + (size_t)(n0 + 8) * FOUT + o0)        = hi;
            *(float2*)(out + half + (size_t)(n0 + 8) * FOUT + o0) = hi;
        }
    }
}

// ---------------------------------------------------------------------------

extern "C" void kernel_launch(void* const* d_in, const int* in_sizes, int n_in,
                              void* d_out, int out_size) {
    (void)in_sizes; (void)n_in; (void)out_size;
    const float* x    = (const float*)d_in[0];
    const float* z    = (const float*)d_in[1];
    const int*   nbr  = (const int*)  d_in[2];
    const float* w1   = (const float*)d_in[3];
    const float* bg   = (const float*)d_in[4];
    const float* bb   = (const float*)d_in[5];
    const float* bm   = (const float*)d_in[6];
    const float* bv   = (const float*)d_in[7];
    const float* w2   = (const float*)d_in[8];
    const float* mlpw = (const float*)d_in[9];
    const float* mlpb = (const float*)d_in[10];
    const float* mg   = (const float*)d_in[11];
    const float* mb2  = (const float*)d_in[12];
    const float* mm   = (const float*)d_in[13];
    const float* mv   = (const float*)d_in[14];
    float* out = (float*)d_out;

    cudaFuncSetAttribute(stage1_kernel, cudaFuncAttributeMaxDynamicSharedMemorySize, S1_SMEM);
    cudaFuncSetAttribute(stage2_kernel, cudaFuncAttributeMaxDynamicSharedMemorySize, S2_SMEM);

    stage1_kernel<<<NCHUNKS, 512, S1_SMEM>>>(x, nbr, w1, w2, bg, bb, bm, bv);
    stage2_kernel<<<NCHUNKS, 512, S2_SMEM>>>(nbr, z, mlpw, mlpb, mg, mb2, mm, mv, out);
}